// round 3
// baseline (speedup 1.0000x reference)
#include <cuda_runtime.h>
#include <math.h>

// ---------------- problem constants ----------------
#define BB   8
#define TT   16
#define CINC 16
#define HID  64
#define CH   (CINC + HID)   // 80
#define HH   64
#define WW   64
#define NPIX (HH * WW)
#define NOUT (BB * HID * NPIX)   // 2,097,152 per tensor

// tiling
#define CCH     8     // input-channel chunk (80 = 10 * 8)
#define PR      18    // patch rows  (16 + 2 halo)
#define PC      34    // patch cols  (32 + 2 halo)
#define PSTRIDE 35    // odd stride -> conflict-free LDS across half-warps

typedef unsigned long long ull;

// double-buffered recurrent state (allocation-free scratch)
__device__ float g_h[2][NOUT];
__device__ float g_c[2][NOUT];

__device__ __forceinline__ ull pack2(float v) {
    ull d; unsigned u = __float_as_uint(v);
    asm("mov.b64 %0, {%1, %1};" : "=l"(d) : "r"(u));
    return d;
}
__device__ __forceinline__ ull fma2(ull a, ull b, ull c) {
    ull d;
    asm("fma.rn.f32x2 %0, %1, %2, %3;" : "=l"(d) : "l"(a), "l"(b), "l"(c));
    return d;
}
__device__ __forceinline__ void unpack2(ull a, float& lo, float& hi) {
    unsigned l, h;
    asm("mov.b64 {%0, %1}, %2;" : "=r"(l), "=r"(h) : "l"(a));
    lo = __uint_as_float(l); hi = __uint_as_float(h);
}
__device__ __forceinline__ float sigf(float x)  { return 1.0f / (1.0f + __expf(-x)); }
__device__ __forceinline__ float tanhg(float x) { return 2.0f / (1.0f + __expf(-2.0f * x)) - 1.0f; }

__global__ void zero_state_kernel() {
    int i = blockIdx.x * blockDim.x + threadIdx.x;
    if (i < NOUT) { g_h[0][i] = 0.0f; g_c[0][i] = 0.0f; }
}

// One fused ConvLSTM step. Tile: 32x16 pixels per block; each thread computes
// 2 adjacent-x pixels for 8 output channels (as 4 oc-pairs in f32x2 lanes).
// Grid: (2, 4, BB * 8). Block: 256 threads (tx 0..15 -> x pair, ty 0..15).
__global__ __launch_bounds__(256, 2)
void step_kernel(const float* __restrict__ x, int t,
                 const float* __restrict__ Wf, const float* __restrict__ bf,
                 const float* __restrict__ Wi, const float* __restrict__ bi,
                 const float* __restrict__ Wc, const float* __restrict__ bc,
                 const float* __restrict__ Wo, const float* __restrict__ bo,
                 int src,
                 float* __restrict__ h_out, float* __restrict__ c_out)
{
    __shared__ float s_in[CCH * PR * PSTRIDE];   // 8*18*35*4 = 20160 B
    __shared__ ull   s_w[CCH * 4 * 28];          // 8*4*28*8  =  7168 B

    const int tid = threadIdx.x;
    const int tx = tid & 15, ty = tid >> 4;
    const int bx = blockIdx.x, by = blockIdx.y;
    const int b   = blockIdx.z >> 3;
    const int oc0 = (blockIdx.z & 7) * 8;

    const float* __restrict__ h_prev = g_h[src];
    const float* __restrict__ c_prev = g_c[src];

    // acc[gate][oc_pair][pixel]; gate: 0=f 1=i 2=g 3=o
    ull acc[4][4][2];
#pragma unroll
    for (int g = 0; g < 4; ++g)
#pragma unroll
        for (int j = 0; j < 4; ++j) { acc[g][j][0] = 0ull; acc[g][j][1] = 0ull; }

    for (int cb = 0; cb < CH; cb += CCH) {
        // --- cooperative load: input patch (8 ch x 18x34, zero-padded SAME) ---
        for (int i = tid; i < CCH * PR * PC; i += 256) {
            int c  = i / (PR * PC);
            int r  = i - c * (PR * PC);
            int py = r / PC, px = r - py * PC;
            int iy = by * 16 + py - 1, ix = bx * 32 + px - 1;
            float v = 0.0f;
            if ((unsigned)iy < HH && (unsigned)ix < WW) {
                int cc = cb + c;
                v = (cc < CINC)
                    ? x[(((size_t)(b * TT + t) * CINC + cc) * HH + iy) * WW + ix]
                    : h_prev[(((size_t)b * HID + (cc - CINC)) * HH + iy) * WW + ix];
            }
            s_in[c * (PR * PSTRIDE) + py * PSTRIDE + px] = v;
        }
        // --- cooperative load: weights interleaved by oc-pair ---
        // s_w[c][ocp][tap] is a 64-bit (w_oc_even, w_oc_odd) pair; tap 0..26
        // are the three conv gates (f,i,g), tap 27 is the linear o-gate weight.
        {
            float* sw = (float*)s_w;
            for (int i = tid; i < CCH * 4 * 28 * 2; i += 256) {
                int half = i & 1;
                int rest = i >> 1;
                int tap  = rest % 28;
                int ocp  = (rest / 28) & 3;
                int c    = rest / (28 * 4);
                int occ  = oc0 + ocp * 2 + half;
                int cc   = cb + c;
                float w;
                if (tap < 9)       w = Wf[(occ * CH + cc) * 9 + tap];
                else if (tap < 18) w = Wi[(occ * CH + cc) * 9 + tap - 9];
                else if (tap < 27) w = Wc[(occ * CH + cc) * 9 + tap - 18];
                else               w = Wo[occ * CH + cc];
                sw[i] = w;
            }
        }
        __syncthreads();

#pragma unroll
        for (int c = 0; c < CCH; ++c) {
            const float* pbase = &s_in[c * (PR * PSTRIDE) + ty * PSTRIDE + 2 * tx];
            // 12 input scalars -> 12 replicated 64-bit packs (ALU pipe)
            ull vp[3][4];
#pragma unroll
            for (int r = 0; r < 3; ++r)
#pragma unroll
                for (int j = 0; j < 4; ++j)
                    vp[r][j] = pack2(pbase[r * PSTRIDE + j]);

#pragma unroll
            for (int ocp = 0; ocp < 4; ++ocp) {
                const ulonglong2* wq = (const ulonglong2*)&s_w[(c * 4 + ocp) * 28];
#pragma unroll
                for (int k = 0; k < 14; ++k) {
                    ulonglong2 wv = wq[k];        // taps 2k, 2k+1 (LDS.128 broadcast)
                    {   // even tap (always < 27: conv)
                        const int tp = 2 * k;
                        const int g = tp / 9, w9 = tp % 9, r = w9 / 3, s = w9 % 3;
                        acc[g][ocp][0] = fma2(wv.x, vp[r][s],     acc[g][ocp][0]);
                        acc[g][ocp][1] = fma2(wv.x, vp[r][s + 1], acc[g][ocp][1]);
                    }
                    {   // odd tap
                        const int tp = 2 * k + 1;
                        if (tp < 27) {
                            const int g = tp / 9, w9 = tp % 9, r = w9 / 3, s = w9 % 3;
                            acc[g][ocp][0] = fma2(wv.y, vp[r][s],     acc[g][ocp][0]);
                            acc[g][ocp][1] = fma2(wv.y, vp[r][s + 1], acc[g][ocp][1]);
                        } else {
                            // tap 27: linear o-gate on center pixel
                            acc[3][ocp][0] = fma2(wv.y, vp[1][1], acc[3][ocp][0]);
                            acc[3][ocp][1] = fma2(wv.y, vp[1][2], acc[3][ocp][1]);
                        }
                    }
                }
            }
        }
        __syncthreads();
    }

    // --- epilogue: bias + activations + LSTM state update ---
    const int gy  = by * 16 + ty;
    const int gx0 = bx * 32 + 2 * tx;
#pragma unroll
    for (int ocp = 0; ocp < 4; ++ocp) {
        float af[2][2], ai[2][2], ag[2][2], ao[2][2];   // [pixel][oc_half]
#pragma unroll
        for (int p = 0; p < 2; ++p) {
            unpack2(acc[0][ocp][p], af[p][0], af[p][1]);
            unpack2(acc[1][ocp][p], ai[p][0], ai[p][1]);
            unpack2(acc[2][ocp][p], ag[p][0], ag[p][1]);
            unpack2(acc[3][ocp][p], ao[p][0], ao[p][1]);
        }
#pragma unroll
        for (int h = 0; h < 2; ++h) {
            const int occ = oc0 + ocp * 2 + h;
            const float bfv = bf[occ], biv = bi[occ], bcv = bc[occ], bov = bo[occ];
#pragma unroll
            for (int p = 0; p < 2; ++p) {
                float f = sigf(af[p][h] + bfv);
                float i = sigf(ai[p][h] + biv);
                float g = tanhg(ag[p][h] + bcv);
                float o = sigf(ao[p][h] + bov);
                size_t idx = (((size_t)b * HID + occ) * HH + gy) * WW + (gx0 + p);
                float cn = c_prev[idx] * f + i * g;
                c_out[idx] = cn;
                h_out[idx] = tanhg(cn) * o;
            }
        }
    }
}

extern "C" void kernel_launch(void* const* d_in, const int* in_sizes, int n_in,
                              void* d_out, int out_size)
{
    const float* x  = (const float*)d_in[0];
    const float* Wf = (const float*)d_in[1];
    const float* bf = (const float*)d_in[2];
    const float* Wi = (const float*)d_in[3];
    const float* bi = (const float*)d_in[4];
    const float* Wc = (const float*)d_in[5];
    const float* bc = (const float*)d_in[6];
    const float* Wo = (const float*)d_in[7];
    const float* bo = (const float*)d_in[8];
    float* out = (float*)d_out;

    float* hbuf = nullptr;
    float* cbuf = nullptr;
    cudaGetSymbolAddress((void**)&hbuf, g_h);
    cudaGetSymbolAddress((void**)&cbuf, g_c);

    zero_state_kernel<<<(NOUT + 255) / 256, 256>>>();

    dim3 grid(2, 4, BB * 8);   // 2 x 4 x 64 = 512 blocks
    for (int t = 0; t < TT; ++t) {
        int src = t & 1, dst = src ^ 1;
        float* h_out = (t == TT - 1) ? out        : hbuf + (size_t)dst * NOUT;
        float* c_out = (t == TT - 1) ? out + NOUT : cbuf + (size_t)dst * NOUT;
        step_kernel<<<grid, 256>>>(x, t, Wf, bf, Wi, bi, Wc, bc, Wo, bo,
                                   src, h_out, c_out);
    }
}

// round 4
// speedup vs baseline: 1.0139x; 1.0139x over previous
#include <cuda_runtime.h>
#include <math.h>

// ---------------- problem constants ----------------
#define BB   8
#define TT   16
#define CINC 16
#define HID  64
#define CH   (CINC + HID)   // 80
#define HH   64
#define WW   64
#define NPIX (HH * WW)
#define NOUT (BB * HID * NPIX)   // 2,097,152 per tensor

// tiling
#define CCH     8     // input-channel chunk (80 = 10 * 8)
#define PR      18    // patch rows  (16 + 2 halo)
#define PC      34    // patch cols  (32 + 2 halo)
#define PSTRIDE 35    // odd stride -> conflict-free LDS across half-warps

typedef unsigned long long ull;

// double-buffered recurrent state (allocation-free scratch)
__device__ float g_h[2][NOUT];
__device__ float g_c[2][NOUT];

__device__ __forceinline__ ull pack2(float v) {
    ull d; unsigned u = __float_as_uint(v);
    asm("mov.b64 %0, {%1, %1};" : "=l"(d) : "r"(u));
    return d;
}
__device__ __forceinline__ ull fma2(ull a, ull b, ull c) {
    ull d;
    asm("fma.rn.f32x2 %0, %1, %2, %3;" : "=l"(d) : "l"(a), "l"(b), "l"(c));
    return d;
}
__device__ __forceinline__ void unpack2(ull a, float& lo, float& hi) {
    unsigned l, h;
    asm("mov.b64 {%0, %1}, %2;" : "=r"(l), "=r"(h) : "l"(a));
    lo = __uint_as_float(l); hi = __uint_as_float(h);
}
__device__ __forceinline__ float sigf(float x)  { return 1.0f / (1.0f + __expf(-x)); }
__device__ __forceinline__ float tanhg(float x) { return 2.0f / (1.0f + __expf(-2.0f * x)) - 1.0f; }

__global__ void zero_state_kernel() {
    int i = blockIdx.x * blockDim.x + threadIdx.x;
    if (i < NOUT) { g_h[0][i] = 0.0f; g_c[0][i] = 0.0f; }
}

// One fused ConvLSTM step. Tile: 32x16 pixels per block; each thread computes
// 2 adjacent-x pixels for 8 output channels (as 4 oc-pairs in f32x2 lanes).
// Grid: (2, 4, BB * 8). Block: 256 threads (tx 0..15 -> x pair, ty 0..15).
__global__ __launch_bounds__(256, 2)
void step_kernel(const float* __restrict__ x, int t,
                 const float* __restrict__ Wf, const float* __restrict__ bf,
                 const float* __restrict__ Wi, const float* __restrict__ bi,
                 const float* __restrict__ Wc, const float* __restrict__ bc,
                 const float* __restrict__ Wo, const float* __restrict__ bo,
                 int src,
                 float* __restrict__ h_out, float* __restrict__ c_out)
{
    __shared__ float s_in[CCH * PR * PSTRIDE];   // 8*18*35*4 = 20160 B
    __shared__ ull   s_w[CCH * 4 * 28];          // 8*4*28*8  =  7168 B

    const int tid = threadIdx.x;
    const int tx = tid & 15, ty = tid >> 4;
    const int bx = blockIdx.x, by = blockIdx.y;
    const int b   = blockIdx.z >> 3;
    const int oc0 = (blockIdx.z & 7) * 8;

    const float* __restrict__ h_prev = g_h[src];
    const float* __restrict__ c_prev = g_c[src];

    // acc[gate][oc_pair][pixel]; gate: 0=f 1=i 2=g 3=o
    ull acc[4][4][2];
#pragma unroll
    for (int g = 0; g < 4; ++g)
#pragma unroll
        for (int j = 0; j < 4; ++j) { acc[g][j][0] = 0ull; acc[g][j][1] = 0ull; }

    for (int cb = 0; cb < CH; cb += CCH) {
        // --- cooperative load: input patch (8 ch x 18x34, zero-padded SAME) ---
        for (int i = tid; i < CCH * PR * PC; i += 256) {
            int c  = i / (PR * PC);
            int r  = i - c * (PR * PC);
            int py = r / PC, px = r - py * PC;
            int iy = by * 16 + py - 1, ix = bx * 32 + px - 1;
            float v = 0.0f;
            if ((unsigned)iy < HH && (unsigned)ix < WW) {
                int cc = cb + c;
                v = (cc < CINC)
                    ? x[(((size_t)(b * TT + t) * CINC + cc) * HH + iy) * WW + ix]
                    : h_prev[(((size_t)b * HID + (cc - CINC)) * HH + iy) * WW + ix];
            }
            s_in[c * (PR * PSTRIDE) + py * PSTRIDE + px] = v;
        }
        // --- cooperative load: weights interleaved by oc-pair ---
        // s_w[c][ocp][tap] is a 64-bit (w_oc_even, w_oc_odd) pair; tap 0..26
        // are the three conv gates (f,i,g), tap 27 is the linear o-gate weight.
        {
            float* sw = (float*)s_w;
            for (int i = tid; i < CCH * 4 * 28 * 2; i += 256) {
                int half = i & 1;
                int rest = i >> 1;
                int tap  = rest % 28;
                int ocp  = (rest / 28) & 3;
                int c    = rest / (28 * 4);
                int occ  = oc0 + ocp * 2 + half;
                int cc   = cb + c;
                float w;
                if (tap < 9)       w = Wf[(occ * CH + cc) * 9 + tap];
                else if (tap < 18) w = Wi[(occ * CH + cc) * 9 + tap - 9];
                else if (tap < 27) w = Wc[(occ * CH + cc) * 9 + tap - 18];
                else               w = Wo[occ * CH + cc];
                sw[i] = w;
            }
        }
        __syncthreads();

#pragma unroll
        for (int c = 0; c < CCH; ++c) {
            const float* pbase = &s_in[c * (PR * PSTRIDE) + ty * PSTRIDE + 2 * tx];
            // 12 input scalars -> 12 replicated 64-bit packs (ALU pipe)
            ull vp[3][4];
#pragma unroll
            for (int r = 0; r < 3; ++r)
#pragma unroll
                for (int j = 0; j < 4; ++j)
                    vp[r][j] = pack2(pbase[r * PSTRIDE + j]);

#pragma unroll
            for (int ocp = 0; ocp < 4; ++ocp) {
                const ulonglong2* wq = (const ulonglong2*)&s_w[(c * 4 + ocp) * 28];
#pragma unroll
                for (int k = 0; k < 14; ++k) {
                    ulonglong2 wv = wq[k];        // taps 2k, 2k+1 (LDS.128 broadcast)
                    {   // even tap (always < 27: conv)
                        const int tp = 2 * k;
                        const int g = tp / 9, w9 = tp % 9, r = w9 / 3, s = w9 % 3;
                        acc[g][ocp][0] = fma2(wv.x, vp[r][s],     acc[g][ocp][0]);
                        acc[g][ocp][1] = fma2(wv.x, vp[r][s + 1], acc[g][ocp][1]);
                    }
                    {   // odd tap
                        const int tp = 2 * k + 1;
                        if (tp < 27) {
                            const int g = tp / 9, w9 = tp % 9, r = w9 / 3, s = w9 % 3;
                            acc[g][ocp][0] = fma2(wv.y, vp[r][s],     acc[g][ocp][0]);
                            acc[g][ocp][1] = fma2(wv.y, vp[r][s + 1], acc[g][ocp][1]);
                        } else {
                            // tap 27: linear o-gate on center pixel
                            acc[3][ocp][0] = fma2(wv.y, vp[1][1], acc[3][ocp][0]);
                            acc[3][ocp][1] = fma2(wv.y, vp[1][2], acc[3][ocp][1]);
                        }
                    }
                }
            }
        }
        __syncthreads();
    }

    // --- epilogue: bias + activations + LSTM state update ---
    const int gy  = by * 16 + ty;
    const int gx0 = bx * 32 + 2 * tx;
#pragma unroll
    for (int ocp = 0; ocp < 4; ++ocp) {
        float af[2][2], ai[2][2], ag[2][2], ao[2][2];   // [pixel][oc_half]
#pragma unroll
        for (int p = 0; p < 2; ++p) {
            unpack2(acc[0][ocp][p], af[p][0], af[p][1]);
            unpack2(acc[1][ocp][p], ai[p][0], ai[p][1]);
            unpack2(acc[2][ocp][p], ag[p][0], ag[p][1]);
            unpack2(acc[3][ocp][p], ao[p][0], ao[p][1]);
        }
#pragma unroll
        for (int h = 0; h < 2; ++h) {
            const int occ = oc0 + ocp * 2 + h;
            const float bfv = bf[occ], biv = bi[occ], bcv = bc[occ], bov = bo[occ];
#pragma unroll
            for (int p = 0; p < 2; ++p) {
                float f = sigf(af[p][h] + bfv);
                float i = sigf(ai[p][h] + biv);
                float g = tanhg(ag[p][h] + bcv);
                float o = sigf(ao[p][h] + bov);
                size_t idx = (((size_t)b * HID + occ) * HH + gy) * WW + (gx0 + p);
                float cn = c_prev[idx] * f + i * g;
                c_out[idx] = cn;
                h_out[idx] = tanhg(cn) * o;
            }
        }
    }
}

extern "C" void kernel_launch(void* const* d_in, const int* in_sizes, int n_in,
                              void* d_out, int out_size)
{
    const float* x  = (const float*)d_in[0];
    const float* Wf = (const float*)d_in[1];
    const float* bf = (const float*)d_in[2];
    const float* Wi = (const float*)d_in[3];
    const float* bi = (const float*)d_in[4];
    const float* Wc = (const float*)d_in[5];
    const float* bc = (const float*)d_in[6];
    const float* Wo = (const float*)d_in[7];
    const float* bo = (const float*)d_in[8];
    float* out = (float*)d_out;

    float* hbuf = nullptr;
    float* cbuf = nullptr;
    cudaGetSymbolAddress((void**)&hbuf, g_h);
    cudaGetSymbolAddress((void**)&cbuf, g_c);

    zero_state_kernel<<<(NOUT + 255) / 256, 256>>>();

    dim3 grid(2, 4, BB * 8);   // 2 x 4 x 64 = 512 blocks
    for (int t = 0; t < TT; ++t) {
        int src = t & 1, dst = src ^ 1;
        float* h_out = (t == TT - 1) ? out        : hbuf + (size_t)dst * NOUT;
        float* c_out = (t == TT - 1) ? out + NOUT : cbuf + (size_t)dst * NOUT;
        step_kernel<<<grid, 256>>>(x, t, Wf, bf, Wi, bi, Wc, bc, Wo, bo,
                                   src, h_out, c_out);
    }
}

// round 8
// speedup vs baseline: 2.5618x; 2.5265x over previous
#include <cuda_runtime.h>
#include <cuda_fp16.h>
#include <cstdint>
#include <math.h>

#define BB 8
#define TT 16
#define CIN 16
#define HID 64
#define NPIX 4096
#define NOUT (BB*HID*NPIX)

typedef unsigned int u32; typedef unsigned long long u64; typedef unsigned short u16;

// ---------------- device scratch (allocation-free) ----------------
__device__ __align__(16) u32 g_x2[BB*TT*NPIX*CIN];     // x as (lo16<<16|hi16) fp16 pair, [bt][pix][ch]
__device__ __align__(16) u32 g_h2[2][BB*NPIX*HID];     // h state, same packing, [b][pix][ch]
__device__ float g_c[BB*NPIX*HID];                     // c state fp32 [b][pix][ch]
__device__ __align__(16) u16 g_Bw[18*256*88];          // 18 blobs: [tap*2+term][n(256)][k(88 padded)]

// ---------------- helpers ----------------
__device__ __forceinline__ u32 s2u(const void* p){u32 a;asm("{ .reg .u64 t; cvta.to.shared.u64 t,%1; cvt.u32.u64 %0,t;}":"=r"(a):"l"(p));return a;}
__device__ __forceinline__ void mb_init(u32 m,u32 c){asm volatile("mbarrier.init.shared.b64 [%0],%1;"::"r"(m),"r"(c):"memory");}
__device__ __forceinline__ void mb_extx(u32 m,u32 b){asm volatile("mbarrier.arrive.expect_tx.shared.b64 _,[%0],%1;"::"r"(m),"r"(b):"memory");}
__device__ __forceinline__ void mb_wait(u32 m,u32 ph){
  u32 done=0;
  while(!done){
    asm volatile("{\n\t.reg .pred p;\n\tmbarrier.try_wait.parity.shared.b64 p,[%1],%2,0x989680;\n\tselp.b32 %0,1,0,p;\n\t}"
                 :"=r"(done):"r"(m),"r"(ph):"memory");
  }
}
__device__ __forceinline__ void cp_bulk(u32 dst,const void* src,u32 bytes,u32 mb){
  asm volatile("cp.async.bulk.shared::cta.global.mbarrier::complete_tx::bytes [%0],[%1],%2,[%3];"
               ::"r"(dst),"l"(src),"r"(bytes),"r"(mb):"memory");
}
#define LDSM4(r0,r1,r2,r3,ad) \
  asm volatile("ldmatrix.sync.aligned.m8n8.x4.shared.b16 {%0,%1,%2,%3},[%4];" \
               :"=r"(r0),"=r"(r1),"=r"(r2),"=r"(r3):"r"(ad))
#define MMA(c,a0,a1,a2,a3,b0,b1) \
  asm volatile("mma.sync.aligned.m16n8k16.row.col.f32.f16.f16.f32 {%0,%1,%2,%3},{%4,%5,%6,%7},{%8,%9},{%0,%1,%2,%3};" \
               :"+f"((c)[0]),"+f"((c)[1]),"+f"((c)[2]),"+f"((c)[3]) \
               :"r"(a0),"r"(a1),"r"(a2),"r"(a3),"r"(b0),"r"(b1))

__device__ __forceinline__ u32 packh(float v){
  __half h=__float2half_rn(v);
  u16 hb=__half_as_ushort(h);
  u16 lb=__half_as_ushort(__float2half_rn(v-__half2float(h)));
  return ((u32)lb<<16)|hb;
}

// ---------------- prep kernels ----------------
__global__ void prep_w(const float* __restrict__ Wf,const float* __restrict__ Wi,
                       const float* __restrict__ Wc,const float* __restrict__ Wo){
  int id=blockIdx.x*blockDim.x+threadIdx.x;
  if(id>=18*256*88) return;
  int k=id%88, n=(id/88)&255, j=id/(88*256);
  int tap=j>>1, term=j&1;
  float v=0.f;
  if(k<80 && (n<192 || tap==4)){
    int gate=n>>6, oc=n&63;
    if(gate==0) v=Wf[(oc*80+k)*9+tap];
    else if(gate==1) v=Wi[(oc*80+k)*9+tap];
    else if(gate==2) v=Wc[(oc*80+k)*9+tap];
    else v=Wo[oc*80+k];
  }
  __half h=__float2half_rn(v);
  u16 val=(term==0)?__half_as_ushort(h):__half_as_ushort(__float2half_rn(v-__half2float(h)));
  g_Bw[id]=val;
}

__global__ void prep_x(const float* __restrict__ x){
  int id=blockIdx.x*blockDim.x+threadIdx.x;
  if(id>=BB*TT*NPIX*CIN) return;
  int c=id&15, pix=(id>>4)&4095, bt=id>>16;
  g_x2[id]=packh(x[((size_t)bt*16+c)*4096+pix]);
}

__global__ void zero_hc(){
  int id=blockIdx.x*blockDim.x+threadIdx.x;
  if(id<BB*NPIX*HID){ g_h2[0][id]=0u; g_c[id]=0.f; }
}

// ---------------- fused step kernel ----------------
// smem layout (dynamic):
//   A hi plane:  [264 slots][88 u16]  = 46464 B   at 0
//   A lo plane:                        46464 B   at 46464
//   B buffers:   2 x 45056 B                     at 92928
//   mbarriers:   2 x 8 B                         at 183040
#define A_LO   46464
#define B_OFF  92928
#define BUF_SZ 45056
#define MB_OFF 183040
#define SMEMSZ 183072

__global__ __launch_bounds__(512,1) void step_kernel(int t,int src,
     const float* __restrict__ bfp,const float* __restrict__ bip,
     const float* __restrict__ bcp,const float* __restrict__ bop,
     float* __restrict__ out)
{
  extern __shared__ __align__(1024) unsigned char smem[];
  const u32 sb=s2u(smem);
  const int tid=threadIdx.x, lane=tid&31, wid=tid>>5;
  const int blk=blockIdx.x, b=blk>>5, ty=blk&31;
  const int pixbase=ty*128;
  const int dst=src^1;

  // ---- stage A patch: 4 rows x 66 cols x 80 ch, hi/lo fp16 planes ----
  {
    u16* aHi=(u16*)smem;
    u16* aLo=(u16*)(smem+A_LO);
    for(int id=tid; id<264*80; id+=512){
      int s=id/80, ch=id-80*s;
      int r=s/66, c2=s-66*r;
      int gy=ty*2-1+r, gx=c2-1;
      u32 v=0u;
      if((unsigned)gy<64u && (unsigned)gx<64u){
        int pix=gy*64+gx;
        v=(ch<16)? g_x2[((size_t)(b*16+t)*4096+pix)*16+ch]
                 : g_h2[src][((size_t)b*4096+pix)*64+(ch-16)];
      }
      aHi[s*88+ch]=(u16)(v&0xffffu);
      aLo[s*88+ch]=(u16)(v>>16);
    }
  }
  const u32 mb=sb+MB_OFF;
  if(tid==0){
    mb_init(mb,1); mb_init(mb+8,1);
    mb_extx(mb,BUF_SZ);   cp_bulk(sb+B_OFF,         (const void*)g_Bw,             BUF_SZ,mb);
    mb_extx(mb+8,BUF_SZ); cp_bulk(sb+B_OFF+BUF_SZ,  (const void*)(g_Bw+22528),     BUF_SZ,mb+8);
  }
  __syncthreads();

  // ---- warp roles: warpM = wid>>2 (32 pix), warpN = (warpM + wid&3)&3 ----
  const int warpM=wid>>2;
  const int warpN=(warpM+(wid&3))&3;
  int nb[4];
  if(warpN<2){ nb[0]=warpN*64; nb[1]=nb[0]+16; nb[2]=nb[0]+32; nb[3]=nb[0]+48; }
  else { int g0=128+(warpN-2)*32, o0=192+(warpN-2)*32;
         nb[0]=g0; nb[1]=g0+16; nb[2]=o0; nb[3]=o0+16; }
  // per-lane ldmatrix offsets
  const u32 aofs=(u32)((lane&15)*176+(lane>>4)*16);
  const u32 bofs=(u32)(((lane&7)+((lane>>4)&1)*8)*176+((lane>>3)&1)*16);
  u32 hofs[2];
#pragma unroll
  for(int half=0;half<2;half++){
    int m0=warpM*32+half*16;
    hofs[half]=(u32)(((m0>>6)*66+(m0&63))*176)+aofs;
  }

  float acc[2][8][4];
#pragma unroll
  for(int h2=0;h2<2;h2++)
#pragma unroll
    for(int q=0;q<8;q++)
#pragma unroll
      for(int e=0;e<4;e++) acc[h2][q][e]=0.f;

  // ---- main loop: 18 blobs (9 taps x {Bh,Bl}) ----
  for(int j=0;j<18;j++){
    const int tap=j>>1;
    mb_wait(mb+(u32)(j&1)*8,(u32)((j>>1)&1));
    const u32 bb=sb+B_OFF+(u32)(j&1)*BUF_SZ;
    const int dy=tap/3-1, dx=tap%3-1;
    const u32 taprow=(u32)(((dy+1)*66+(dx+1))*176);
    const int npA=(warpN<2||tap==4)?4:2;
    const int nterm=(j&1)?1:2;
#pragma unroll
    for(int s=0;s<2;s++){
      if(s>=nterm) break;
      const u32 aplane=sb+(((j&1)==0&&s==1)?A_LO:0u);
#pragma unroll
      for(int kc=0;kc<5;kc++){
        u32 bf_[4][4];
#pragma unroll
        for(int p=0;p<4;p++){
          if(p<npA){
            LDSM4(bf_[p][0],bf_[p][1],bf_[p][2],bf_[p][3],
                  bb+(u32)nb[p]*176u+(u32)kc*32u+bofs);
          }
        }
#pragma unroll
        for(int half=0;half<2;half++){
          u32 a0,a1,a2,a3;
          LDSM4(a0,a1,a2,a3, aplane+hofs[half]+taprow+(u32)kc*32u);
#pragma unroll
          for(int p=0;p<4;p++){
            if(p<npA){
              MMA(acc[half][2*p],  a0,a1,a2,a3, bf_[p][0],bf_[p][1]);
              MMA(acc[half][2*p+1],a0,a1,a2,a3, bf_[p][2],bf_[p][3]);
            }
          }
        }
      }
    }
    __syncthreads();
    if(tid==0 && j<16){
      mb_extx(mb+(u32)(j&1)*8,BUF_SZ);
      cp_bulk(bb,(const void*)(g_Bw+(size_t)(j+2)*22528),BUF_SZ,mb+(u32)(j&1)*8);
    }
  }

  // ---- cross-warp gate exchange via smem (reuse A/B region) ----
  __syncthreads();
  float* sg=(float*)smem;   // [128 pix][256 n] f32 = 131072 B
#pragma unroll
  for(int half=0;half<2;half++)
#pragma unroll
    for(int q=0;q<8;q++)
#pragma unroll
      for(int e=0;e<4;e++){
        int pix=warpM*32+half*16+(lane>>2)+((e>>1)*8);
        int n=nb[q>>1]+(q&1)*8+(lane&3)*2+(e&1);
        sg[pix*256+n]=acc[half][q][e];
      }
  __syncthreads();

  // ---- fused LSTM update ----
  for(int it=tid; it<8192; it+=512){
    int pix=it>>6, oc=it&63;
    float f =sg[pix*256+oc];
    float i2=sg[pix*256+64+oc];
    float gg=sg[pix*256+128+oc];
    float oo=sg[pix*256+192+oc];
    f =1.f/(1.f+__expf(-(f +bfp[oc])));
    i2=1.f/(1.f+__expf(-(i2+bip[oc])));
    gg=2.f/(1.f+__expf(-2.f*(gg+bcp[oc])))-1.f;
    oo=1.f/(1.f+__expf(-(oo+bop[oc])));
    int pixg=pixbase+pix;
    size_t ci=((size_t)b*4096+pixg)*64+oc;
    float cn=g_c[ci]*f+i2*gg;
    g_c[ci]=cn;
    float hh=(2.f/(1.f+__expf(-2.f*cn))-1.f)*oo;
    if(t<TT-1){
      g_h2[dst][ci]=packh(hh);
    } else {
      out[((size_t)(b*64+oc))*4096+pixg]=hh;
      out[(size_t)NOUT+((size_t)(b*64+oc))*4096+pixg]=cn;
    }
  }
}

// ---------------- host launch ----------------
extern "C" void kernel_launch(void* const* d_in, const int* in_sizes, int n_in,
                              void* d_out, int out_size)
{
  const float* x  =(const float*)d_in[0];
  const float* Wf =(const float*)d_in[1];
  const float* bf =(const float*)d_in[2];
  const float* Wi =(const float*)d_in[3];
  const float* bi =(const float*)d_in[4];
  const float* Wc =(const float*)d_in[5];
  const float* bc =(const float*)d_in[6];
  const float* Wo =(const float*)d_in[7];
  const float* bo =(const float*)d_in[8];
  float* out=(float*)d_out;

  cudaFuncSetAttribute(step_kernel, cudaFuncAttributeMaxDynamicSharedMemorySize, SMEMSZ);

  prep_w<<<(18*256*88+255)/256,256>>>(Wf,Wi,Wc,Wo);
  prep_x<<<(BB*TT*NPIX*CIN+255)/256,256>>>(x);
  zero_hc<<<(BB*NPIX*HID+255)/256,256>>>();

  for(int t=0;t<TT;t++){
    step_kernel<<<256,512,SMEMSZ>>>(t, t&1, bf,bi,bc,bo, out);
  }
}